// round 14
// baseline (speedup 1.0000x reference)
#include <cuda_runtime.h>

#define NB 4
#define NT 16384
#define NCOND 80
#define NLAY 40
#define TT 472
#define HALO 40
#define TTH 512
#define TILES_PER_B 35
#define NTHREADS 1024

// pair-duplicated transposed weights [k][(c,c)] (floats within wd)
#define D0D 0
#define D1D 2048
#define FD  4096
#define GD  6144
#define CFD 8192
#define CGD 13312
#define OD  18432
#define WTOT 20480

#define SMEM_FLOATS (64*TTH + WTOT + 32)
#define SMEM_BYTES  (SMEM_FLOATS * 4)

typedef unsigned long long u64;

__device__ __forceinline__ u64 pk(float lo, float hi) {
    u64 r; asm("mov.b64 %0,{%1,%2};" : "=l"(r) : "f"(lo), "f"(hi)); return r;
}
__device__ __forceinline__ void upk(u64 v, float& a, float& b) {
    asm("mov.b64 {%0,%1},%2;" : "=f"(a), "=f"(b) : "l"(v));
}
__device__ __forceinline__ u64 fma2(u64 a, u64 b, u64 c) {
    u64 d; asm("fma.rn.f32x2 %0,%1,%2,%3;" : "=l"(d) : "l"(a), "l"(b), "l"(c)); return d;
}
__device__ __forceinline__ u64 add2(u64 a, u64 b) {
    u64 d; asm("add.rn.f32x2 %0,%1,%2;" : "=l"(d) : "l"(a), "l"(b)); return d;
}
__device__ __forceinline__ float fast_sigmoid(float v) {
    v = fminf(fmaxf(v, -30.f), 30.f);
    return __fdividef(1.f, 1.f + __expf(-v));
}
__device__ __forceinline__ float fast_tanh(float v) {
    v = fminf(fmaxf(v, -15.f), 15.f);
    float e2 = __expf(2.f * v);
    return __fdividef(e2 - 1.f, e2 + 1.f);
}

__global__ void __launch_bounds__(NTHREADS, 1)
wavenet_kernel(const float* __restrict__ x, const float* __restrict__ h,
               const float* __restrict__ start_w, const float* __restrict__ dil_w,
               const float* __restrict__ f_w, const float* __restrict__ g_w,
               const float* __restrict__ cf_w, const float* __restrict__ cg_w,
               const float* __restrict__ out_w, const float* __restrict__ end1_w,
               const float* __restrict__ end2_w, float* __restrict__ out)
{
    extern __shared__ float smem[];
    float* res  = smem;               // [32][TTH]
    float* ybuf = smem + 32 * TTH;    // [32][TTH]
    float* wd   = smem + 64 * TTH;    // [WTOT] dup weights
    float* sw   = wd + WTOT;          // [32]

    const int tid = threadIdx.x;
    const int b   = blockIdx.x / TILES_PER_B;
    const int tc  = blockIdx.x % TILES_PER_B;
    const int tgb = tc * TT - HALO;

    if (tid < 32) sw[tid] = start_w[tid];
    for (int idx = tid; idx < 32 * TTH; idx += NTHREADS) {
        int ch = idx >> 9, lt = idx & (TTH - 1);
        int tg = tgb + lt;
        float xv = (tg >= 0 && tg < NT) ? x[b * NT + tg] : 0.f;
        res[idx] = start_w[ch] * xv;
    }
    __syncthreads();

    // thread tile: 4 ch x 4 t (2 time-pairs), lanes contiguous in time
    const int c0  = (tid >> 7) * 4;        // 0,4,...,28
    const int lt0 = (tid & 127) * 4;       // 0..508
    const int tg0 = tgb + lt0;
    const bool hval = (tg0 >= 0 && tg0 + 4 <= NT);
    const float* hb = h + ((size_t)(b * NCOND)) * NT + tg0;

    for (int l = 0; l < NLAY; ++l) {
        // ---- stage weights [k][(c,c)] duplicated; dest-major conflict-free STS ----
        {
            const float* dl  = dil_w + l * 2048;
            const float* fl  = f_w   + l * 1024;
            const float* gl  = g_w   + l * 1024;
            const float* cfl = cf_w  + l * 2560;
            const float* cgl = cg_w  + l * 2560;
            const float* ol  = out_w + l * 1024;
            for (int j = tid; j < 1024; j += NTHREADS) {     // dil
                int i = j >> 5, c = j & 31;
                float2 wv = *(const float2*)(dl + (c * 32 + i) * 2);
                *(float2*)(wd + D0D + (i * 32 + c) * 2) = make_float2(wv.x, wv.x);
                *(float2*)(wd + D1D + (i * 32 + c) * 2) = make_float2(wv.y, wv.y);
            }
            for (int j = tid; j < 1024; j += NTHREADS) {     // f, g
                int k = j >> 5, c = j & 31;
                float vf = fl[c * 32 + k];
                float vg = gl[c * 32 + k];
                *(float2*)(wd + FD + (k * 32 + c) * 2) = make_float2(vf, vf);
                *(float2*)(wd + GD + (k * 32 + c) * 2) = make_float2(vg, vg);
            }
            for (int j = tid; j < 2560; j += NTHREADS) {     // cf, cg
                int k = j >> 5, c = j & 31;
                float vf = cfl[c * 80 + k];
                float vg = cgl[c * 80 + k];
                *(float2*)(wd + CFD + (k * 32 + c) * 2) = make_float2(vf, vf);
                *(float2*)(wd + CGD + (k * 32 + c) * 2) = make_float2(vg, vg);
            }
            for (int j = tid; j < 1024; j += NTHREADS) {     // out
                int k = j >> 5, c = j & 31;
                float v = ol[c * 32 + k];
                *(float2*)(wd + OD + (k * 32 + c) * 2) = make_float2(v, v);
            }
        }
        __syncthreads();

        // ---- G1: y[c,t] = W0[c,i]*res[i,t-1] + W1[c,i]*res[i,t] ----
        {
            u64 acc[4][2];
            #pragma unroll
            for (int a = 0; a < 4; ++a) { acc[a][0] = 0ULL; acc[a][1] = 0ULL; }

            #pragma unroll 2
            for (int i = 0; i < 32; ++i) {
                const float* rr = res + i * TTH + lt0;
                ulonglong2 A = *(const ulonglong2*)rr;       // (r0,r1)(r2,r3)
                float r0, r1, r2, r3;
                upk(A.x, r0, r1); upk(A.y, r2, r3);
                float rm1 = (lt0 > 0) ? rr[-1] : 0.f;
                u64 d0 = pk(rm1, r0), d1 = pk(r1, r2);
                const float* w0p = wd + D0D + (i * 32 + c0) * 2;
                const float* w1p = wd + D1D + (i * 32 + c0) * 2;
                ulonglong2 w0A = *(const ulonglong2*)w0p;
                ulonglong2 w0B = *(const ulonglong2*)(w0p + 4);
                ulonglong2 w1A = *(const ulonglong2*)w1p;
                ulonglong2 w1B = *(const ulonglong2*)(w1p + 4);
                u64 w0_[4] = {w0A.x, w0A.y, w0B.x, w0B.y};
                u64 w1_[4] = {w1A.x, w1A.y, w1B.x, w1B.y};
                #pragma unroll
                for (int cc = 0; cc < 4; ++cc) {
                    acc[cc][0] = fma2(d0,  w0_[cc], acc[cc][0]);
                    acc[cc][0] = fma2(A.x, w1_[cc], acc[cc][0]);
                    acc[cc][1] = fma2(d1,  w0_[cc], acc[cc][1]);
                    acc[cc][1] = fma2(A.y, w1_[cc], acc[cc][1]);
                }
            }
            #pragma unroll
            for (int cc = 0; cc < 4; ++cc)
                *(ulonglong2*)(ybuf + (c0 + cc) * TTH + lt0) =
                    make_ulonglong2(acc[cc][0], acc[cc][1]);
        }
        __syncthreads();

        // ---- G2: z = tanh(F@y + CF@h) * sigmoid(G@y + CG@h) ----
        float z0[4], z1[4], z2[4], z3[4];
        {
            u64 pf[4][2], pg[4][2];
            #pragma unroll
            for (int a = 0; a < 4; ++a) {
                pf[a][0] = 0ULL; pf[a][1] = 0ULL;
                pg[a][0] = 0ULL; pg[a][1] = 0ULL;
            }

            if (hval) {  // conditioning pass (batched LDG.128, no packing)
                #pragma unroll 2
                for (int k = 0; k < NCOND; k += 2) {
                    ulonglong2 h0 = *(const ulonglong2*)(hb + (size_t)k * NT);
                    ulonglong2 h1 = *(const ulonglong2*)(hb + (size_t)(k + 1) * NT);
                    #pragma unroll
                    for (int q = 0; q < 2; ++q) {
                        ulonglong2 hv = q ? h1 : h0;
                        const float* wfp = wd + CFD + ((k + q) * 32 + c0) * 2;
                        const float* wgp = wd + CGD + ((k + q) * 32 + c0) * 2;
                        ulonglong2 fA = *(const ulonglong2*)wfp;
                        ulonglong2 fB = *(const ulonglong2*)(wfp + 4);
                        ulonglong2 gA = *(const ulonglong2*)wgp;
                        ulonglong2 gB = *(const ulonglong2*)(wgp + 4);
                        u64 wf_[4] = {fA.x, fA.y, fB.x, fB.y};
                        u64 wg_[4] = {gA.x, gA.y, gB.x, gB.y};
                        #pragma unroll
                        for (int cc = 0; cc < 4; ++cc) {
                            pf[cc][0] = fma2(hv.x, wf_[cc], pf[cc][0]);
                            pf[cc][1] = fma2(hv.y, wf_[cc], pf[cc][1]);
                            pg[cc][0] = fma2(hv.x, wg_[cc], pg[cc][0]);
                            pg[cc][1] = fma2(hv.y, wg_[cc], pg[cc][1]);
                        }
                    }
                }
            }
            // y pass
            #pragma unroll 4
            for (int k = 0; k < 32; ++k) {
                ulonglong2 yv = *(const ulonglong2*)(ybuf + k * TTH + lt0);
                const float* wfp = wd + FD + (k * 32 + c0) * 2;
                const float* wgp = wd + GD + (k * 32 + c0) * 2;
                ulonglong2 fA = *(const ulonglong2*)wfp;
                ulonglong2 fB = *(const ulonglong2*)(wfp + 4);
                ulonglong2 gA = *(const ulonglong2*)wgp;
                ulonglong2 gB = *(const ulonglong2*)(wgp + 4);
                u64 wf_[4] = {fA.x, fA.y, fB.x, fB.y};
                u64 wg_[4] = {gA.x, gA.y, gB.x, gB.y};
                #pragma unroll
                for (int cc = 0; cc < 4; ++cc) {
                    pf[cc][0] = fma2(yv.x, wf_[cc], pf[cc][0]);
                    pf[cc][1] = fma2(yv.y, wf_[cc], pf[cc][1]);
                    pg[cc][0] = fma2(yv.x, wg_[cc], pg[cc][0]);
                    pg[cc][1] = fma2(yv.y, wg_[cc], pg[cc][1]);
                }
            }
            #pragma unroll
            for (int cc = 0; cc < 4; ++cc) {
                float f0, f1, f2, f3, g0, g1, g2, g3;
                upk(pf[cc][0], f0, f1); upk(pf[cc][1], f2, f3);
                upk(pg[cc][0], g0, g1); upk(pg[cc][1], g2, g3);
                z0[cc] = fast_tanh(f0) * fast_sigmoid(g0);
                z1[cc] = fast_tanh(f1) * fast_sigmoid(g1);
                z2[cc] = fast_tanh(f2) * fast_sigmoid(g2);
                z3[cc] = fast_tanh(f3) * fast_sigmoid(g3);
            }
        }
        __syncthreads();   // all reads of y done
        #pragma unroll
        for (int cc = 0; cc < 4; ++cc)
            *(float4*)(ybuf + (c0 + cc) * TTH + lt0) =
                make_float4(z0[cc], z1[cc], z2[cc], z3[cc]);
        __syncthreads();   // z complete

        // ---- G3: res += Ow @ z ----
        {
            u64 acc[4][2];
            #pragma unroll
            for (int a = 0; a < 4; ++a) { acc[a][0] = 0ULL; acc[a][1] = 0ULL; }

            #pragma unroll 4
            for (int k = 0; k < 32; ++k) {
                ulonglong2 zv = *(const ulonglong2*)(ybuf + k * TTH + lt0);
                const float* wp = wd + OD + (k * 32 + c0) * 2;
                ulonglong2 wA = *(const ulonglong2*)wp;
                ulonglong2 wB = *(const ulonglong2*)(wp + 4);
                u64 w_[4] = {wA.x, wA.y, wB.x, wB.y};
                #pragma unroll
                for (int cc = 0; cc < 4; ++cc) {
                    acc[cc][0] = fma2(zv.x, w_[cc], acc[cc][0]);
                    acc[cc][1] = fma2(zv.y, w_[cc], acc[cc][1]);
                }
            }
            if (tg0 >= 0) {
                #pragma unroll
                for (int cc = 0; cc < 4; ++cc) {
                    float* rp = res + (c0 + cc) * TTH + lt0;
                    ulonglong2 rv = *(const ulonglong2*)rp;
                    *(ulonglong2*)rp = make_ulonglong2(add2(rv.x, acc[cc][0]),
                                                       add2(rv.y, acc[cc][1]));
                }
            }
        }
        __syncthreads();
    }

    // ---- relu(skip) -> ybuf; stage end1 dup [k][(s,s)] into wd ----
    for (int idx = tid; idx < 32 * TTH; idx += NTHREADS) {
        int ch = idx >> 9, lt = idx & (TTH - 1);
        int tg = tgb + lt;
        float xv = (tg >= 0 && tg < NT) ? x[b * NT + tg] : 0.f;
        ybuf[idx] = fmaxf(res[idx] - sw[ch] * xv, 0.f);
    }
    for (int j = tid; j < 8192; j += NTHREADS) {   // conflict-free dup staging
        int k = j >> 8, s = j & 255;
        float v = end1_w[s * 32 + k];
        *(float2*)(wd + (k * 256 + s) * 2) = make_float2(v, v);
    }
    __syncthreads();

    // ---- end head: chunks of 64 timesteps; ebuf[256][64] reuses res ----
    float* ebuf = res;
    const int s0 = (tid >> 4) * 4;   // 0..252 step 4
    const int t4 = (tid & 15) * 4;   // 0..60
    for (int chunk = 0; chunk < 8; ++chunk) {
        const int ltc = HALO + chunk * 64 + t4;
        const bool active = (ltc < TTH);    // chunk 7 partial
        u64 a0[4], a1[4];
        #pragma unroll
        for (int t = 0; t < 4; ++t) { a0[t] = 0ULL; a1[t] = 0ULL; }

        if (active) {  // E1: e = relu(end1 @ skip), time-pair lanes, dup weights
            #pragma unroll 2
            for (int k = 0; k < 32; ++k) {
                ulonglong2 yv = *(const ulonglong2*)(ybuf + k * TTH + ltc);
                const float* wp = wd + (k * 256 + s0) * 2;
                ulonglong2 wA = *(const ulonglong2*)wp;
                ulonglong2 wB = *(const ulonglong2*)(wp + 4);
                u64 w_[4] = {wA.x, wA.y, wB.x, wB.y};
                #pragma unroll
                for (int ss = 0; ss < 4; ++ss) {
                    a0[ss] = fma2(yv.x, w_[ss], a0[ss]);
                    a1[ss] = fma2(yv.y, w_[ss], a1[ss]);
                }
            }
        }
        __syncthreads();   // prior chunk's E2 reads of ebuf complete
        if (active) {
            #pragma unroll
            for (int ss = 0; ss < 4; ++ss) {
                float v0, v1, v2, v3;
                upk(a0[ss], v0, v1); upk(a1[ss], v2, v3);
                *(float4*)(ebuf + (s0 + ss) * 64 + t4) =
                    make_float4(fmaxf(v0, 0.f), fmaxf(v1, 0.f),
                                fmaxf(v2, 0.f), fmaxf(v3, 0.f));
            }
        }
        __syncthreads();   // e complete
        if (active) {  // E2: logit = end2 @ e, float4 k-major weight loads
            u64 acc2[4][2];
            #pragma unroll
            for (int a = 0; a < 4; ++a) { acc2[a][0] = 0ULL; acc2[a][1] = 0ULL; }
            #pragma unroll 2
            for (int k4 = 0; k4 < 64; ++k4) {
                ulonglong2 ev0 = *(const ulonglong2*)(ebuf + (k4 * 4 + 0) * 64 + t4);
                ulonglong2 ev1 = *(const ulonglong2*)(ebuf + (k4 * 4 + 1) * 64 + t4);
                ulonglong2 ev2 = *(const ulonglong2*)(ebuf + (k4 * 4 + 2) * 64 + t4);
                ulonglong2 ev3 = *(const ulonglong2*)(ebuf + (k4 * 4 + 3) * 64 + t4);
                #pragma unroll
                for (int cc = 0; cc < 4; ++cc) {
                    float4 w4 = __ldg((const float4*)(end2_w + (s0 + cc) * 256 + k4 * 4));
                    u64 wp0 = pk(w4.x, w4.x), wp1 = pk(w4.y, w4.y),
                        wp2 = pk(w4.z, w4.z), wp3 = pk(w4.w, w4.w);
                    acc2[cc][0] = fma2(ev0.x, wp0, acc2[cc][0]);
                    acc2[cc][1] = fma2(ev0.y, wp0, acc2[cc][1]);
                    acc2[cc][0] = fma2(ev1.x, wp1, acc2[cc][0]);
                    acc2[cc][1] = fma2(ev1.y, wp1, acc2[cc][1]);
                    acc2[cc][0] = fma2(ev2.x, wp2, acc2[cc][0]);
                    acc2[cc][1] = fma2(ev2.y, wp2, acc2[cc][1]);
                    acc2[cc][0] = fma2(ev3.x, wp3, acc2[cc][0]);
                    acc2[cc][1] = fma2(ev3.y, wp3, acc2[cc][1]);
                }
            }
            int tgc = tgb + ltc;
            #pragma unroll
            for (int cc = 0; cc < 4; ++cc) {
                float* op = out + ((size_t)(b * 256 + s0 + cc)) * NT + tgc;
                if (tgc + 4 <= NT) {
                    *(u64*)op       = acc2[cc][0];
                    *(u64*)(op + 2) = acc2[cc][1];
                } else {
                    #pragma unroll
                    for (int p = 0; p < 2; ++p) {
                        float a0_, a1_; upk(acc2[cc][p], a0_, a1_);
                        if (tgc + 2 * p     < NT) op[2 * p]     = a0_;
                        if (tgc + 2 * p + 1 < NT) op[2 * p + 1] = a1_;
                    }
                }
            }
        }
        __syncthreads();   // all E2 reads of ebuf done before next chunk overwrites
    }
}

extern "C" void kernel_launch(void* const* d_in, const int* in_sizes, int n_in,
                              void* d_out, int out_size) {
    const float* x       = (const float*)d_in[0];
    const float* h       = (const float*)d_in[1];
    const float* start_w = (const float*)d_in[2];
    const float* dil_w   = (const float*)d_in[3];
    const float* f_w     = (const float*)d_in[4];
    const float* g_w     = (const float*)d_in[5];
    const float* cf_w    = (const float*)d_in[6];
    const float* cg_w    = (const float*)d_in[7];
    const float* out_w   = (const float*)d_in[8];
    const float* end1_w  = (const float*)d_in[9];
    const float* end2_w  = (const float*)d_in[10];
    float* out = (float*)d_out;

    cudaFuncSetAttribute(wavenet_kernel,
                         cudaFuncAttributeMaxDynamicSharedMemorySize, SMEM_BYTES);
    wavenet_kernel<<<NB * TILES_PER_B, NTHREADS, SMEM_BYTES>>>(
        x, h, start_w, dil_w, f_w, g_w, cf_w, cg_w, out_w, end1_w, end2_w, out);
}

// round 15
// speedup vs baseline: 1.4031x; 1.4031x over previous
#include <cuda_runtime.h>

#define NB 4
#define NT 16384
#define NCOND 80
#define NLAY 40
#define TT 472
#define HALO 40
#define TTH 512
#define TILES_PER_B 35
#define NTHREADS 512

// per-layer transposed weights [k][c] (floats), two staging slots
#define D0T 0
#define D1T 1024
#define F2T 2048
#define G2T 3072
#define CF2T 4096
#define CG2T 6656
#define O2T 9216
#define WLAY 10240
#define WTOT (2*WLAY)

#define SMEM_FLOATS (64*TTH + WTOT + 32)
#define SMEM_BYTES  (SMEM_FLOATS * 4)

typedef unsigned long long u64;

__device__ __forceinline__ u64 pk(float lo, float hi) {
    u64 r; asm("mov.b64 %0,{%1,%2};" : "=l"(r) : "f"(lo), "f"(hi)); return r;
}
__device__ __forceinline__ void upk(u64 v, float& a, float& b) {
    asm("mov.b64 {%0,%1},%2;" : "=f"(a), "=f"(b) : "l"(v));
}
__device__ __forceinline__ u64 fma2(u64 a, u64 b, u64 c) {
    u64 d; asm("fma.rn.f32x2 %0,%1,%2,%3;" : "=l"(d) : "l"(a), "l"(b), "l"(c)); return d;
}
__device__ __forceinline__ float fast_sigmoid(float v) {
    v = fminf(fmaxf(v, -30.f), 30.f);
    return __fdividef(1.f, 1.f + __expf(-v));
}
__device__ __forceinline__ float fast_tanh(float v) {
    v = fminf(fmaxf(v, -15.f), 15.f);
    float e2 = __expf(2.f * v);
    return __fdividef(e2 - 1.f, e2 + 1.f);
}

__global__ void __launch_bounds__(NTHREADS, 1)
wavenet_kernel(const float* __restrict__ x, const float* __restrict__ h,
               const float* __restrict__ start_w, const float* __restrict__ dil_w,
               const float* __restrict__ f_w, const float* __restrict__ g_w,
               const float* __restrict__ cf_w, const float* __restrict__ cg_w,
               const float* __restrict__ out_w, const float* __restrict__ end1_w,
               const float* __restrict__ end2_w, float* __restrict__ out)
{
    extern __shared__ float smem[];
    float* res  = smem;               // [32][TTH]
    float* ybuf = smem + 32 * TTH;    // [32][TTH]
    float* wd   = smem + 64 * TTH;    // [2][WLAY]
    float* sw   = wd + WTOT;          // [32]

    const int tid = threadIdx.x;
    const int b   = blockIdx.x / TILES_PER_B;
    const int tc  = blockIdx.x % TILES_PER_B;
    const int tgb = tc * TT - HALO;

    if (tid < 32) sw[tid] = start_w[tid];
    for (int idx = tid; idx < 32 * TTH; idx += NTHREADS) {
        int ch = idx >> 9, lt = idx & (TTH - 1);
        int tg = tgb + lt;
        float xv = (tg >= 0 && tg < NT) ? x[b * NT + tg] : 0.f;
        res[idx] = start_w[ch] * xv;
    }
    __syncthreads();

    // thread tile: 8 ch (4 channel-pairs) x 4 t, lanes contiguous in time
    const int c0  = (tid >> 7) * 8;        // 0,8,16,24
    const int lt0 = (tid & 127) * 4;       // 0..508
    const int tg0 = tgb + lt0;
    const bool hval = (tg0 >= 0 && tg0 + 4 <= NT);
    const float* hb = h + ((size_t)(b * NCOND)) * NT + tg0;

    for (int l = 0; l < NLAY; l += 2) {
        // ---- stage TWO layers' weights transposed [k][c]; conflict-free STS ----
        #pragma unroll
        for (int s = 0; s < 2; ++s) {
            float* w = wd + s * WLAY;
            const float* dl  = dil_w + (l + s) * 2048;
            const float* fl  = f_w   + (l + s) * 1024;
            const float* gl  = g_w   + (l + s) * 1024;
            const float* cfl = cf_w  + (l + s) * 2560;
            const float* cgl = cg_w  + (l + s) * 2560;
            const float* ol  = out_w + (l + s) * 1024;
            for (int j = tid; j < 1024; j += NTHREADS) {     // dil
                int i = j >> 5, c = j & 31;
                float2 wv = *(const float2*)(dl + (c * 32 + i) * 2);
                w[D0T + j] = wv.x;
                w[D1T + j] = wv.y;
            }
            for (int j = tid; j < 512; j += NTHREADS) {      // f, g
                int k2 = j >> 5, c = j & 31;
                float2 vf = *(const float2*)(fl + c * 32 + 2 * k2);
                float2 vg = *(const float2*)(gl + c * 32 + 2 * k2);
                w[F2T + (2 * k2) * 32 + c]     = vf.x;
                w[F2T + (2 * k2 + 1) * 32 + c] = vf.y;
                w[G2T + (2 * k2) * 32 + c]     = vg.x;
                w[G2T + (2 * k2 + 1) * 32 + c] = vg.y;
            }
            for (int j = tid; j < 1280; j += NTHREADS) {     // cf, cg
                int k2 = j >> 5, c = j & 31;
                float2 vf = *(const float2*)(cfl + c * 80 + 2 * k2);
                float2 vg = *(const float2*)(cgl + c * 80 + 2 * k2);
                w[CF2T + (2 * k2) * 32 + c]     = vf.x;
                w[CF2T + (2 * k2 + 1) * 32 + c] = vf.y;
                w[CG2T + (2 * k2) * 32 + c]     = vg.x;
                w[CG2T + (2 * k2 + 1) * 32 + c] = vg.y;
            }
            for (int j = tid; j < 512; j += NTHREADS) {      // out
                int k2 = j >> 5, c = j & 31;
                float2 v = *(const float2*)(ol + c * 32 + 2 * k2);
                w[O2T + (2 * k2) * 32 + c]     = v.x;
                w[O2T + (2 * k2 + 1) * 32 + c] = v.y;
            }
        }
        __syncthreads();

        #pragma unroll 1
        for (int s = 0; s < 2; ++s) {
            const float* wdl = wd + s * WLAY;

            // ---- G1: y[c,t] = W0[c,i]*res[i,t-1] + W1[c,i]*res[i,t] ----
            {
                u64 acc[4][4];   // [channel-pair][t]
                #pragma unroll
                for (int p = 0; p < 4; ++p)
                    #pragma unroll
                    for (int t = 0; t < 4; ++t) acc[p][t] = 0ULL;

                #pragma unroll 2
                for (int i = 0; i < 32; ++i) {
                    const float* rr = res + i * TTH + lt0;
                    float4 rv = *(const float4*)rr;
                    float rm1 = (lt0 > 0) ? rr[-1] : 0.f;
                    u64 pv[5] = { pk(rm1, rm1), pk(rv.x, rv.x), pk(rv.y, rv.y),
                                  pk(rv.z, rv.z), pk(rv.w, rv.w) };
                    const float* w0p = wdl + D0T + i * 32 + c0;
                    const float* w1p = wdl + D1T + i * 32 + c0;
                    ulonglong2 w0A = *(const ulonglong2*)w0p;
                    ulonglong2 w0B = *(const ulonglong2*)(w0p + 4);
                    ulonglong2 w1A = *(const ulonglong2*)w1p;
                    ulonglong2 w1B = *(const ulonglong2*)(w1p + 4);
                    u64 w0_[4] = {w0A.x, w0A.y, w0B.x, w0B.y};
                    u64 w1_[4] = {w1A.x, w1A.y, w1B.x, w1B.y};
                    #pragma unroll
                    for (int p = 0; p < 4; ++p)
                        #pragma unroll
                        for (int t = 0; t < 4; ++t) {
                            acc[p][t] = fma2(pv[t],     w0_[p], acc[p][t]);
                            acc[p][t] = fma2(pv[t + 1], w1_[p], acc[p][t]);
                        }
                }
                #pragma unroll
                for (int p = 0; p < 4; ++p) {
                    float va[4], vb[4];
                    #pragma unroll
                    for (int t = 0; t < 4; ++t) upk(acc[p][t], va[t], vb[t]);
                    *(float4*)(ybuf + (c0 + 2 * p) * TTH + lt0) =
                        make_float4(va[0], va[1], va[2], va[3]);
                    *(float4*)(ybuf + (c0 + 2 * p + 1) * TTH + lt0) =
                        make_float4(vb[0], vb[1], vb[2], vb[3]);
                }
            }
            __syncthreads();

            // ---- G2: z = tanh(F@y + CF@h) * sigmoid(G@y + CG@h) ----
            float zz[8][4];
            {
                u64 pf[4][4], pg[4][4];
                #pragma unroll
                for (int p = 0; p < 4; ++p)
                    #pragma unroll
                    for (int t = 0; t < 4; ++t) { pf[p][t] = 0ULL; pg[p][t] = 0ULL; }

                if (hval) {  // conditioning pass
                    #pragma unroll 2
                    for (int k = 0; k < NCOND; k += 2) {
                        float4 hA = *(const float4*)(hb + (size_t)k * NT);
                        float4 hB = *(const float4*)(hb + (size_t)(k + 1) * NT);
                        #pragma unroll
                        for (int q = 0; q < 2; ++q) {
                            float4 hv = q ? hB : hA;
                            u64 pvv[4] = { pk(hv.x, hv.x), pk(hv.y, hv.y),
                                           pk(hv.z, hv.z), pk(hv.w, hv.w) };
                            const float* wfp = wdl + CF2T + (k + q) * 32 + c0;
                            const float* wgp = wdl + CG2T + (k + q) * 32 + c0;
                            ulonglong2 fA = *(const ulonglong2*)wfp;
                            ulonglong2 fB = *(const ulonglong2*)(wfp + 4);
                            ulonglong2 gA = *(const ulonglong2*)wgp;
                            ulonglong2 gB = *(const ulonglong2*)(wgp + 4);
                            u64 wf_[4] = {fA.x, fA.y, fB.x, fB.y};
                            u64 wg_[4] = {gA.x, gA.y, gB.x, gB.y};
                            #pragma unroll
                            for (int p = 0; p < 4; ++p)
                                #pragma unroll
                                for (int t = 0; t < 4; ++t) {
                                    pf[p][t] = fma2(pvv[t], wf_[p], pf[p][t]);
                                    pg[p][t] = fma2(pvv[t], wg_[p], pg[p][t]);
                                }
                        }
                    }
                }
                // y pass
                #pragma unroll 2
                for (int k = 0; k < 32; ++k) {
                    float4 yv = *(const float4*)(ybuf + k * TTH + lt0);
                    u64 pvv[4] = { pk(yv.x, yv.x), pk(yv.y, yv.y),
                                   pk(yv.z, yv.z), pk(yv.w, yv.w) };
                    const float* wfp = wdl + F2T + k * 32 + c0;
                    const float* wgp = wdl + G2T + k * 32 + c0;
                    ulonglong2 fA = *(const ulonglong2*)wfp;
                    ulonglong2 fB = *(const ulonglong2*)(wfp + 4);
                    ulonglong2 gA = *(const ulonglong2*)wgp;
                    ulonglong2 gB = *(const ulonglong2*)(wgp + 4);
                    u64 wf_[4] = {fA.x, fA.y, fB.x, fB.y};
                    u64 wg_[4] = {gA.x, gA.y, gB.x, gB.y};
                    #pragma unroll
                    for (int p = 0; p < 4; ++p)
                        #pragma unroll
                        for (int t = 0; t < 4; ++t) {
                            pf[p][t] = fma2(pvv[t], wf_[p], pf[p][t]);
                            pg[p][t] = fma2(pvv[t], wg_[p], pg[p][t]);
                        }
                }
                #pragma unroll
                for (int p = 0; p < 4; ++p)
                    #pragma unroll
                    for (int t = 0; t < 4; ++t) {
                        float fa, fb, ga, gb;
                        upk(pf[p][t], fa, fb); upk(pg[p][t], ga, gb);
                        zz[2 * p][t]     = fast_tanh(fa) * fast_sigmoid(ga);
                        zz[2 * p + 1][t] = fast_tanh(fb) * fast_sigmoid(gb);
                    }
            }
            __syncthreads();   // all reads of y done
            #pragma unroll
            for (int c = 0; c < 8; ++c)
                *(float4*)(ybuf + (c0 + c) * TTH + lt0) =
                    make_float4(zz[c][0], zz[c][1], zz[c][2], zz[c][3]);
            __syncthreads();   // z complete

            // ---- G3: res += Ow @ z ----
            {
                u64 acc[4][4];
                #pragma unroll
                for (int p = 0; p < 4; ++p)
                    #pragma unroll
                    for (int t = 0; t < 4; ++t) acc[p][t] = 0ULL;

                #pragma unroll 2
                for (int k = 0; k < 32; ++k) {
                    float4 zv = *(const float4*)(ybuf + k * TTH + lt0);
                    u64 pvv[4] = { pk(zv.x, zv.x), pk(zv.y, zv.y),
                                   pk(zv.z, zv.z), pk(zv.w, zv.w) };
                    const float* wp = wdl + O2T + k * 32 + c0;
                    ulonglong2 wA = *(const ulonglong2*)wp;
                    ulonglong2 wB = *(const ulonglong2*)(wp + 4);
                    u64 w_[4] = {wA.x, wA.y, wB.x, wB.y};
                    #pragma unroll
                    for (int p = 0; p < 4; ++p)
                        #pragma unroll
                        for (int t = 0; t < 4; ++t)
                            acc[p][t] = fma2(pvv[t], w_[p], acc[p][t]);
                }
                if (tg0 >= 0) {
                    #pragma unroll
                    for (int p = 0; p < 4; ++p) {
                        float va[4], vb[4];
                        #pragma unroll
                        for (int t = 0; t < 4; ++t) upk(acc[p][t], va[t], vb[t]);
                        float* ra = res + (c0 + 2 * p) * TTH + lt0;
                        float* rb = res + (c0 + 2 * p + 1) * TTH + lt0;
                        float4 qa = *(float4*)ra, qb = *(float4*)rb;
                        *(float4*)ra = make_float4(qa.x + va[0], qa.y + va[1],
                                                   qa.z + va[2], qa.w + va[3]);
                        *(float4*)rb = make_float4(qb.x + vb[0], qb.y + vb[1],
                                                   qb.z + vb[2], qb.w + vb[3]);
                    }
                }
            }
            __syncthreads();
        }
    }

    // ---- relu(skip) -> ybuf; stage end1 transposed [k][s] into wd ----
    for (int idx = tid; idx < 32 * TTH; idx += NTHREADS) {
        int ch = idx >> 9, lt = idx & (TTH - 1);
        int tg = tgb + lt;
        float xv = (tg >= 0 && tg < NT) ? x[b * NT + tg] : 0.f;
        ybuf[idx] = fmaxf(res[idx] - sw[ch] * xv, 0.f);
    }
    for (int j = tid; j < 8192; j += NTHREADS) {   // dest [k][s]: conflict-free STS
        int k = j >> 8, s = j & 255;
        wd[j] = end1_w[s * 32 + k];
    }
    __syncthreads();

    // ---- end head: chunks of 64 timesteps; ebuf[256][64] reuses res ----
    // thread tile: 8 skip-ch x 4 t : s0 = (tid>>4)*8 (32 blocks), t4 = (tid&15)*4
    float* ebuf = res;
    const int s0 = (tid >> 4) * 8;
    const int t4 = (tid & 15) * 4;
    for (int chunk = 0; chunk < 8; ++chunk) {
        const int ltc = HALO + chunk * 64 + t4;
        const bool active = (ltc < TTH);    // chunk 7 partial
        u64 a_[4][4];
        #pragma unroll
        for (int p = 0; p < 4; ++p)
            #pragma unroll
            for (int t = 0; t < 4; ++t) a_[p][t] = 0ULL;

        if (active) {  // E1: e = relu(end1 @ skip), channel-pair lanes
            #pragma unroll 2
            for (int k = 0; k < 32; ++k) {
                float4 yv = *(const float4*)(ybuf + k * TTH + ltc);
                u64 pvv[4] = { pk(yv.x, yv.x), pk(yv.y, yv.y),
                               pk(yv.z, yv.z), pk(yv.w, yv.w) };
                const float* wp = wd + k * 256 + s0;
                ulonglong2 wA = *(const ulonglong2*)wp;
                ulonglong2 wB = *(const ulonglong2*)(wp + 4);
                u64 w_[4] = {wA.x, wA.y, wB.x, wB.y};
                #pragma unroll
                for (int p = 0; p < 4; ++p)
                    #pragma unroll
                    for (int t = 0; t < 4; ++t)
                        a_[p][t] = fma2(pvv[t], w_[p], a_[p][t]);
            }
        }
        __syncthreads();   // prior chunk's E2 reads of ebuf complete
        if (active) {
            #pragma unroll
            for (int p = 0; p < 4; ++p) {
                float va[4], vb[4];
                #pragma unroll
                for (int t = 0; t < 4; ++t) upk(a_[p][t], va[t], vb[t]);
                *(float4*)(ebuf + (s0 + 2 * p) * 64 + t4) =
                    make_float4(fmaxf(va[0],0.f), fmaxf(va[1],0.f),
                                fmaxf(va[2],0.f), fmaxf(va[3],0.f));
                *(float4*)(ebuf + (s0 + 2 * p + 1) * 64 + t4) =
                    make_float4(fmaxf(vb[0],0.f), fmaxf(vb[1],0.f),
                                fmaxf(vb[2],0.f), fmaxf(vb[3],0.f));
            }
        }
        __syncthreads();   // e complete
        if (active) {  // E2: logit = end2 @ e (8 out-ch), float4 k-major weights
            u64 acc2[8][2];
            #pragma unroll
            for (int c = 0; c < 8; ++c) { acc2[c][0] = 0ULL; acc2[c][1] = 0ULL; }
            #pragma unroll 1
            for (int k4 = 0; k4 < 64; ++k4) {
                ulonglong2 ev0 = *(const ulonglong2*)(ebuf + (k4 * 4 + 0) * 64 + t4);
                ulonglong2 ev1 = *(const ulonglong2*)(ebuf + (k4 * 4 + 1) * 64 + t4);
                ulonglong2 ev2 = *(const ulonglong2*)(ebuf + (k4 * 4 + 2) * 64 + t4);
                ulonglong2 ev3 = *(const ulonglong2*)(ebuf + (k4 * 4 + 3) * 64 + t4);
                #pragma unroll
                for (int c = 0; c < 8; ++c) {
                    float4 w4 = __ldg((const float4*)(end2_w + (s0 + c) * 256 + k4 * 4));
                    u64 wp0 = pk(w4.x, w4.x), wp1 = pk(w4.y, w4.y),
                        wp2 = pk(w4.z, w4.z), wp3 = pk(w4.w, w4.w);
                    acc2[c][0] = fma2(ev0.x, wp0, acc2[c][0]);
                    acc2[c][1] = fma2(ev0.y, wp0, acc2[c][1]);
                    acc2[c][0] = fma2(ev1.x, wp1, acc2[c][0]);
                    acc2[c][1] = fma2(ev1.y, wp1, acc2[c][1]);
                    acc2[c][0] = fma2(ev2.x, wp2, acc2[c][0]);
                    acc2[c][1] = fma2(ev2.y, wp2, acc2[c][1]);
                    acc2[c][0] = fma2(ev3.x, wp3, acc2[c][0]);
                    acc2[c][1] = fma2(ev3.y, wp3, acc2[c][1]);
                }
            }
            int tgc = tgb + ltc;
            #pragma unroll
            for (int c = 0; c < 8; ++c) {
                float* op = out + ((size_t)(b * 256 + s0 + c)) * NT + tgc;
                if (tgc + 4 <= NT) {
                    *(u64*)op       = acc2[c][0];
                    *(u64*)(op + 2) = acc2[c][1];
                } else {
                    #pragma unroll
                    for (int p = 0; p < 2; ++p) {
                        float a0_, a1_; upk(acc2[c][p], a0_, a1_);
                        if (tgc + 2 * p     < NT) op[2 * p]     = a0_;
                        if (tgc + 2 * p + 1 < NT) op[2 * p + 1] = a1_;
                    }
                }
            }
        }
        __syncthreads();   // all E2 reads of ebuf done before next chunk overwrites
    }
}

extern "C" void kernel_launch(void* const* d_in, const int* in_sizes, int n_in,
                              void* d_out, int out_size) {
    const float* x       = (const float*)d_in[0];
    const float* h       = (const float*)d_in[1];
    const float* start_w = (const float*)d_in[2];
    const float* dil_w   = (const float*)d_in[3];
    const float* f_w     = (const float*)d_in[4];
    const float* g_w     = (const float*)d_in[5];
    const float* cf_w    = (const float*)d_in[6];
    const float* cg_w    = (const float*)d_in[7];
    const float* out_w   = (const float*)d_in[8];
    const float* end1_w  = (const float*)d_in[9];
    const float* end2_w  = (const float*)d_in[10];
    float* out = (float*)d_out;

    cudaFuncSetAttribute(wavenet_kernel,
                         cudaFuncAttributeMaxDynamicSharedMemorySize, SMEM_BYTES);
    wavenet_kernel<<<NB * TILES_PER_B, NTHREADS, SMEM_BYTES>>>(
        x, h, start_w, dil_w, f_w, g_w, cf_w, cg_w, out_w, end1_w, end2_w, out);
}